// round 4
// baseline (speedup 1.0000x reference)
#include <cuda_runtime.h>
#include <math.h>

#define Dd 1024
#define Mm 8192
#define Hh 16
#define Bb 64
#define HDd 64

// ---------------- scratch (device globals; no allocation allowed) ----------
__device__ float g_q[Bb * Dd];
__device__ float g_qh[Bb * Dd];
__device__ float g_Wck[Dd * Dd];
__device__ float g_Wcv[Dd * Dd];
__device__ float g_bck[Dd];
__device__ float g_bcv[Dd];
__device__ float g_kh[Mm * Dd];
__device__ float g_vh[Mm * Dd];
__device__ float g_scores[Bb * Hh * Mm];
__device__ float g_ctx[Bb * Dd];
__device__ float g_ms[Bb * Dd];
__device__ float g_gin[Bb * 2 * Dd];
__device__ float g_g1[Bb * Dd];
__device__ float g_gated[Bb * Dd];
__device__ float g_comb[Bb * 2 * Dd];
__device__ float g_i1[Bb * 2 * Dd];

// ---------------- generic tiled SGEMM --------------------------------------
// TN mode (NN_MODE=false): C[m,n] = sum_k A[m,k] * B[n,k]    (B is N x K row-major)
// NN mode (NN_MODE=true):  C[m,n] = sum_k A[m,k] * B[k,n]    (B is K x N row-major)
// Batched via blockIdx.z = batch * nsplit + split. Split-K accumulates with atomics.
// Epilogue: v = alpha*acc (+bias[n]) -> act(0 none,1 relu,2 sigmoid) -> (*mul[m,n])
template <int BM, int BN, int BK, int TM, int TN, bool NN_MODE, bool ATOMIC>
__global__ void __launch_bounds__(256) gemm_k(
    const float* __restrict__ A, const float* __restrict__ Bm, float* __restrict__ C,
    int Mdim, int Ndim, int Kdim,
    int lda, int ldb, int ldc,
    int sA, int sB, int sC,
    int nsplit, float alpha,
    const float* __restrict__ bias, int act, const float* __restrict__ mul)
{
    constexpr int TX = BN / TN;
    constexpr int TY = BM / TM;
    static_assert(TX * TY == 256, "256 threads");

    __shared__ float As[BK * BM];
    __shared__ float Bs[BK * BN];

    const int tid = threadIdx.x;
    const int tx = tid % TX;
    const int ty = tid / TX;

    const int z = blockIdx.z;
    const int batch = z / nsplit;
    const int split = z % nsplit;
    A += batch * sA;
    Bm += batch * sB;
    C += batch * sC;

    const int Ks = Kdim / nsplit;
    int k0 = split * Ks;
    const int kend = k0 + Ks;

    const int m0 = blockIdx.y * BM;
    const int n0 = blockIdx.x * BN;

    float acc[TM][TN];
#pragma unroll
    for (int i = 0; i < TM; i++)
#pragma unroll
        for (int j = 0; j < TN; j++) acc[i][j] = 0.0f;

    constexpr int AK4 = BK / 4;           // float4 chunks per A row
    const int aRow = tid / AK4;
    const int aC4 = (tid % AK4) * 4;

    for (; k0 < kend; k0 += BK) {
        // ---- load A tile (BM x BK), store transposed As[k][m]
        {
            float4 av = *(const float4*)&A[(m0 + aRow) * lda + k0 + aC4];
            As[(aC4 + 0) * BM + aRow] = av.x;
            As[(aC4 + 1) * BM + aRow] = av.y;
            As[(aC4 + 2) * BM + aRow] = av.z;
            As[(aC4 + 3) * BM + aRow] = av.w;
        }
        // ---- load B tile
        if (NN_MODE) {
            constexpr int BN4 = BN / 4;
            const int bK = tid / BN4;
            const int bC = (tid % BN4) * 4;
            float4 bv = *(const float4*)&Bm[(k0 + bK) * ldb + n0 + bC];
            *(float4*)&Bs[bK * BN + bC] = bv;
        } else {
            const int bRow = tid / AK4;
            const int bC4 = (tid % AK4) * 4;
            float4 bv = *(const float4*)&Bm[(n0 + bRow) * ldb + k0 + bC4];
            Bs[(bC4 + 0) * BN + bRow] = bv.x;
            Bs[(bC4 + 1) * BN + bRow] = bv.y;
            Bs[(bC4 + 2) * BN + bRow] = bv.z;
            Bs[(bC4 + 3) * BN + bRow] = bv.w;
        }
        __syncthreads();

#pragma unroll
        for (int k = 0; k < BK; k++) {
            float ar[TM], br[TN];
#pragma unroll
            for (int i = 0; i < TM; i += 4)
                *(float4*)&ar[i] = *(const float4*)&As[k * BM + ty * TM + i];
#pragma unroll
            for (int j = 0; j < TN; j += 4)
                *(float4*)&br[j] = *(const float4*)&Bs[k * BN + tx * TN + j];
#pragma unroll
            for (int i = 0; i < TM; i++)
#pragma unroll
                for (int j = 0; j < TN; j++) acc[i][j] = fmaf(ar[i], br[j], acc[i][j]);
        }
        __syncthreads();
    }

    // ---- epilogue
#pragma unroll
    for (int i = 0; i < TM; i++) {
        const int r = m0 + ty * TM + i;
#pragma unroll
        for (int j = 0; j < TN; j++) {
            const int c = n0 + tx * TN + j;
            float v = acc[i][j] * alpha;
            if (ATOMIC) {
                atomicAdd(&C[r * ldc + c], v);
            } else {
                if (bias) v += bias[c];
                if (act == 1) v = fmaxf(v, 0.0f);
                else if (act == 2) v = 1.0f / (1.0f + expf(-v));
                if (mul) v *= mul[r * ldc + c];
                C[r * ldc + c] = v;
            }
        }
    }
}

// ---------------- small helper kernels -------------------------------------
// out[row] = b2[row] + dot(W[row,:], b1)   (rows = Dd)
__global__ void bias_combine_k(const float* __restrict__ W, const float* __restrict__ b1,
                               const float* __restrict__ b2, float* __restrict__ out)
{
    const int row = blockIdx.x * blockDim.y + threadIdx.y;
    const int lane = threadIdx.x;
    float s = 0.0f;
    for (int c = lane; c < Dd; c += 32) s += W[row * Dd + c] * b1[c];
#pragma unroll
    for (int o = 16; o; o >>= 1) s += __shfl_down_sync(0xffffffffu, s, o);
    if (lane == 0) out[row] = s + b2[row];
}

__global__ void zero_k(float* p, int n)
{
    const int i = blockIdx.x * 256 + threadIdx.x;
    if (i < n) p[i] = 0.0f;
}

// o[B x 2D] = concat(a[B x D], b[B x D])
__global__ void concat_k(const float* __restrict__ a, const float* __restrict__ b,
                         float* __restrict__ o)
{
    const int i = blockIdx.x * 256 + threadIdx.x;
    if (i >= Bb * 2 * Dd) return;
    const int r = i / (2 * Dd);
    const int c = i % (2 * Dd);
    o[i] = (c < Dd) ? a[r * Dd + c] : b[r * Dd + c - Dd];
}

// in-place softmax over rows of length Mm; grid = B*H rows
__global__ void softmax_k(float* __restrict__ s)
{
    float* row = s + (size_t)blockIdx.x * Mm;
    __shared__ float red[256];
    const int t = threadIdx.x;

    float mx = -1e30f;
    for (int i = t; i < Mm; i += 256) mx = fmaxf(mx, row[i]);
    red[t] = mx;
    __syncthreads();
    for (int o = 128; o; o >>= 1) {
        if (t < o) red[t] = fmaxf(red[t], red[t + o]);
        __syncthreads();
    }
    mx = red[0];
    __syncthreads();

    float sum = 0.0f;
    for (int i = t; i < Mm; i += 256) {
        float e = expf(row[i] - mx);
        row[i] = e;
        sum += e;
    }
    red[t] = sum;
    __syncthreads();
    for (int o = 128; o; o >>= 1) {
        if (t < o) red[t] += red[t + o];
        __syncthreads();
    }
    const float inv = 1.0f / red[0];
    for (int i = t; i < Mm; i += 256) row[i] *= inv;
}

// ---------------- launch ----------------------------------------------------
extern "C" void kernel_launch(void* const* d_in, const int* in_sizes, int n_in,
                              void* d_out, int out_size)
{
    (void)in_sizes; (void)n_in; (void)out_size;
    const float* x    = (const float*)d_in[0];
    const float* mk   = (const float*)d_in[1];
    const float* mv   = (const float*)d_in[2];
    const float* Wq   = (const float*)d_in[3];
    const float* bq   = (const float*)d_in[4];
    const float* Wk   = (const float*)d_in[5];
    const float* bk   = (const float*)d_in[6];
    const float* Wv   = (const float*)d_in[7];
    const float* bv   = (const float*)d_in[8];
    const float* ipw  = (const float*)d_in[9];   // (3D, D)
    const float* ipb  = (const float*)d_in[10];  // (3D,)
    const float* outw = (const float*)d_in[11];
    const float* outb = (const float*)d_in[12];
    const float* gW1  = (const float*)d_in[13];  // (D, 2D)
    const float* gb1  = (const float*)d_in[14];
    const float* gW2  = (const float*)d_in[15];
    const float* gb2  = (const float*)d_in[16];
    const float* iW1  = (const float*)d_in[17];  // (2D, 2D)
    const float* ib1  = (const float*)d_in[18];
    const float* iW2  = (const float*)d_in[19];  // (D, 2D)
    const float* ib2  = (const float*)d_in[20];
    float* out = (float*)d_out;

    const float* Wiq = ipw;
    const float* Wik = ipw + Dd * Dd;
    const float* Wiv = ipw + 2 * Dd * Dd;
    const float* biq = ipb;
    const float* bik = ipb + Dd;
    const float* biv = ipb + 2 * Dd;

    // resolve device-global addresses (host side; not an allocation)
    float *q, *qh, *Wck, *Wcv, *bck, *bcv, *kh, *vh, *scores, *ctx, *ms, *gin, *g1, *gated, *comb, *i1;
    cudaGetSymbolAddress((void**)&q, g_q);
    cudaGetSymbolAddress((void**)&qh, g_qh);
    cudaGetSymbolAddress((void**)&Wck, g_Wck);
    cudaGetSymbolAddress((void**)&Wcv, g_Wcv);
    cudaGetSymbolAddress((void**)&bck, g_bck);
    cudaGetSymbolAddress((void**)&bcv, g_bcv);
    cudaGetSymbolAddress((void**)&kh, g_kh);
    cudaGetSymbolAddress((void**)&vh, g_vh);
    cudaGetSymbolAddress((void**)&scores, g_scores);
    cudaGetSymbolAddress((void**)&ctx, g_ctx);
    cudaGetSymbolAddress((void**)&ms, g_ms);
    cudaGetSymbolAddress((void**)&gin, g_gin);
    cudaGetSymbolAddress((void**)&g1, g_g1);
    cudaGetSymbolAddress((void**)&gated, g_gated);
    cudaGetSymbolAddress((void**)&comb, g_comb);
    cudaGetSymbolAddress((void**)&i1, g_i1);

    const dim3 blk(256);

    // 1) combined biases: bck = bik + Wik@bk ; bcv = biv + Wiv@bv
    bias_combine_k<<<Dd / 8, dim3(32, 8)>>>(Wik, bk, bik, bck);
    bias_combine_k<<<Dd / 8, dim3(32, 8)>>>(Wiv, bv, biv, bcv);

    // 2) combined weights: Wck = Wik @ Wk, Wcv = Wiv @ Wv   (NN, 1024^3)
    gemm_k<128, 128, 8, 8, 8, true, false><<<dim3(8, 8, 1), blk>>>(
        Wik, Wk, Wck, Dd, Dd, Dd, Dd, Dd, Dd, 0, 0, 0, 1, 1.0f, nullptr, 0, nullptr);
    gemm_k<128, 128, 8, 8, 8, true, false><<<dim3(8, 8, 1), blk>>>(
        Wiv, Wv, Wcv, Dd, Dd, Dd, Dd, Dd, Dd, 0, 0, 0, 1, 1.0f, nullptr, 0, nullptr);

    // 3) kh = keys @ Wck^T + bck ; vh = values @ Wcv^T + bcv   (TN, 8192x1024x1024)
    gemm_k<128, 128, 8, 8, 8, false, false><<<dim3(8, 64, 1), blk>>>(
        mk, Wck, kh, Mm, Dd, Dd, Dd, Dd, Dd, 0, 0, 0, 1, 1.0f, bck, 0, nullptr);
    gemm_k<128, 128, 8, 8, 8, false, false><<<dim3(8, 64, 1), blk>>>(
        mv, Wcv, vh, Mm, Dd, Dd, Dd, Dd, Dd, 0, 0, 0, 1, 1.0f, bcv, 0, nullptr);

    // 4) q = x @ Wq^T + bq ; qh = q @ Wiq^T + biq   (TN small)
    gemm_k<64, 64, 16, 4, 4, false, false><<<dim3(16, 1, 1), blk>>>(
        x, Wq, q, Bb, Dd, Dd, Dd, Dd, Dd, 0, 0, 0, 1, 1.0f, bq, 0, nullptr);
    gemm_k<64, 64, 16, 4, 4, false, false><<<dim3(16, 1, 1), blk>>>(
        q, Wiq, qh, Bb, Dd, Dd, Dd, Dd, Dd, 0, 0, 0, 1, 1.0f, biq, 0, nullptr);

    // 5) scores[b,h,m] = 0.125 * sum_d qh[b,h*64+d]*kh[m,h*64+d]   (batched TN per head)
    gemm_k<64, 64, 16, 4, 4, false, false><<<dim3(Mm / 64, 1, Hh), blk>>>(
        qh, kh, scores, Bb, Mm, HDd, Dd, Dd, Hh * Mm, HDd, HDd, Mm,
        1, 0.125f, nullptr, 0, nullptr);

    // 6) softmax over m
    softmax_k<<<Bb * Hh, blk>>>(scores);

    // 7) ctx = attn @ vh   (batched NN per head, split-K=8, atomic accumulate)
    zero_k<<<(Bb * Dd + 255) / 256, blk>>>(ctx, Bb * Dd);
    gemm_k<64, 64, 16, 4, 4, true, true><<<dim3(1, 1, Hh * 8), blk>>>(
        scores, vh, ctx, Bb, HDd, Mm, Hh * Mm, Dd, Dd, Mm, HDd, HDd,
        8, 1.0f, nullptr, 0, nullptr);

    // 8) memory_signal = ctx @ out_w^T + out_b
    gemm_k<64, 64, 16, 4, 4, false, false><<<dim3(16, 1, 1), blk>>>(
        ctx, outw, ms, Bb, Dd, Dd, Dd, Dd, Dd, 0, 0, 0, 1, 1.0f, outb, 0, nullptr);

    // 9) gate path: gin = [x, ms]; g1 = relu(gin@gW1^T+gb1); gated = sigmoid(g1@gW2^T+gb2)*ms
    concat_k<<<(Bb * 2 * Dd + 255) / 256, blk>>>(x, ms, gin);
    gemm_k<64, 64, 16, 4, 4, false, false><<<dim3(16, 1, 1), blk>>>(
        gin, gW1, g1, Bb, Dd, 2 * Dd, 2 * Dd, 2 * Dd, Dd, 0, 0, 0, 1, 1.0f, gb1, 1, nullptr);
    gemm_k<64, 64, 16, 4, 4, false, false><<<dim3(16, 1, 1), blk>>>(
        g1, gW2, gated, Bb, Dd, Dd, Dd, Dd, Dd, 0, 0, 0, 1, 1.0f, gb2, 2, ms);

    // 10) output path: comb = [x, gated]; i1 = relu(comb@iW1^T+ib1); out = i1@iW2^T+ib2
    concat_k<<<(Bb * 2 * Dd + 255) / 256, blk>>>(x, gated, comb);
    gemm_k<64, 64, 16, 4, 4, false, false><<<dim3(32, 1, 1), blk>>>(
        comb, iW1, i1, Bb, 2 * Dd, 2 * Dd, 2 * Dd, 2 * Dd, 2 * Dd, 0, 0, 0, 1, 1.0f, ib1, 1, nullptr);
    gemm_k<64, 64, 16, 4, 4, false, false><<<dim3(16, 1, 1), blk>>>(
        i1, iW2, out, Bb, Dd, 2 * Dd, 2 * Dd, 2 * Dd, Dd, 0, 0, 0, 1, 1.0f, ib2, 0, nullptr);
}

// round 5
// speedup vs baseline: 1.0009x; 1.0009x over previous
#include <cuda_runtime.h>
#include <math.h>

#define Dd 1024
#define Mm 8192
#define Hh 16
#define Bb 64
#define HDd 64

// ---------------- scratch (device globals; no allocation allowed) ----------
__device__ float g_q[Bb * Dd];
__device__ float g_qh[Bb * Dd];
__device__ float g_Wck[Dd * Dd];
__device__ float g_Wcv[Dd * Dd];
__device__ float g_bck[Dd];
__device__ float g_bcv[Dd];
__device__ float g_kh[Mm * Dd];
__device__ float g_vh[Mm * Dd];
__device__ float g_scores[Bb * Hh * Mm];
__device__ float g_ctx[Bb * Dd];
__device__ float g_ms[Bb * Dd];
__device__ float g_gin[Bb * 2 * Dd];
__device__ float g_g1[Bb * Dd];
__device__ float g_gated[Bb * Dd];
__device__ float g_comb[Bb * 2 * Dd];
__device__ float g_i1[Bb * 2 * Dd];

// ---------------- generic tiled SGEMM --------------------------------------
// TN mode (NN_MODE=false): C[m,n] = sum_k A[m,k] * B[n,k]    (B is N x K row-major)
// NN mode (NN_MODE=true):  C[m,n] = sum_k A[m,k] * B[k,n]    (B is K x N row-major)
// Batched via blockIdx.z = batch * nsplit + split. Split-K accumulates with atomics.
// Epilogue: v = alpha*acc (+bias[n]) -> act(0 none,1 relu,2 sigmoid) -> (*mul[m,n])
template <int BM, int BN, int BK, int TM, int TN, bool NN_MODE, bool ATOMIC>
__global__ void __launch_bounds__(256) gemm_k(
    const float* __restrict__ A, const float* __restrict__ Bm, float* __restrict__ C,
    int Mdim, int Ndim, int Kdim,
    int lda, int ldb, int ldc,
    int sA, int sB, int sC,
    int nsplit, float alpha,
    const float* __restrict__ bias, int act, const float* __restrict__ mul)
{
    constexpr int TX = BN / TN;
    constexpr int TY = BM / TM;
    static_assert(TX * TY == 256, "256 threads");

    __shared__ float As[BK * BM];
    __shared__ float Bs[BK * BN];

    const int tid = threadIdx.x;
    const int tx = tid % TX;
    const int ty = tid / TX;

    const int z = blockIdx.z;
    const int batch = z / nsplit;
    const int split = z % nsplit;
    A += batch * sA;
    Bm += batch * sB;
    C += batch * sC;

    const int Ks = Kdim / nsplit;
    int k0 = split * Ks;
    const int kend = k0 + Ks;

    const int m0 = blockIdx.y * BM;
    const int n0 = blockIdx.x * BN;

    float acc[TM][TN];
#pragma unroll
    for (int i = 0; i < TM; i++)
#pragma unroll
        for (int j = 0; j < TN; j++) acc[i][j] = 0.0f;

    constexpr int AK4 = BK / 4;           // float4 chunks per A row
    const int aRow = tid / AK4;
    const int aC4 = (tid % AK4) * 4;

    for (; k0 < kend; k0 += BK) {
        // ---- load A tile (BM x BK), store transposed As[k][m]
        {
            float4 av = *(const float4*)&A[(m0 + aRow) * lda + k0 + aC4];
            As[(aC4 + 0) * BM + aRow] = av.x;
            As[(aC4 + 1) * BM + aRow] = av.y;
            As[(aC4 + 2) * BM + aRow] = av.z;
            As[(aC4 + 3) * BM + aRow] = av.w;
        }
        // ---- load B tile
        if (NN_MODE) {
            constexpr int BN4 = BN / 4;
            const int bK = tid / BN4;
            const int bC = (tid % BN4) * 4;
            float4 bv = *(const float4*)&Bm[(k0 + bK) * ldb + n0 + bC];
            *(float4*)&Bs[bK * BN + bC] = bv;
        } else {
            const int bRow = tid / AK4;
            const int bC4 = (tid % AK4) * 4;
            float4 bv = *(const float4*)&Bm[(n0 + bRow) * ldb + k0 + bC4];
            Bs[(bC4 + 0) * BN + bRow] = bv.x;
            Bs[(bC4 + 1) * BN + bRow] = bv.y;
            Bs[(bC4 + 2) * BN + bRow] = bv.z;
            Bs[(bC4 + 3) * BN + bRow] = bv.w;
        }
        __syncthreads();

#pragma unroll
        for (int k = 0; k < BK; k++) {
            float ar[TM], br[TN];
#pragma unroll
            for (int i = 0; i < TM; i += 4)
                *(float4*)&ar[i] = *(const float4*)&As[k * BM + ty * TM + i];
#pragma unroll
            for (int j = 0; j < TN; j += 4)
                *(float4*)&br[j] = *(const float4*)&Bs[k * BN + tx * TN + j];
#pragma unroll
            for (int i = 0; i < TM; i++)
#pragma unroll
                for (int j = 0; j < TN; j++) acc[i][j] = fmaf(ar[i], br[j], acc[i][j]);
        }
        __syncthreads();
    }

    // ---- epilogue
#pragma unroll
    for (int i = 0; i < TM; i++) {
        const int r = m0 + ty * TM + i;
#pragma unroll
        for (int j = 0; j < TN; j++) {
            const int c = n0 + tx * TN + j;
            float v = acc[i][j] * alpha;
            if (ATOMIC) {
                atomicAdd(&C[r * ldc + c], v);
            } else {
                if (bias) v += bias[c];
                if (act == 1) v = fmaxf(v, 0.0f);
                else if (act == 2) v = 1.0f / (1.0f + expf(-v));
                if (mul) v *= mul[r * ldc + c];
                C[r * ldc + c] = v;
            }
        }
    }
}

// ---------------- small helper kernels -------------------------------------
// out[row] = b2[row] + dot(W[row,:], b1)   (rows = Dd)
__global__ void bias_combine_k(const float* __restrict__ W, const float* __restrict__ b1,
                               const float* __restrict__ b2, float* __restrict__ out)
{
    const int row = blockIdx.x * blockDim.y + threadIdx.y;
    const int lane = threadIdx.x;
    float s = 0.0f;
    for (int c = lane; c < Dd; c += 32) s += W[row * Dd + c] * b1[c];
#pragma unroll
    for (int o = 16; o; o >>= 1) s += __shfl_down_sync(0xffffffffu, s, o);
    if (lane == 0) out[row] = s + b2[row];
}

__global__ void zero_k(float* p, int n)
{
    const int i = blockIdx.x * 256 + threadIdx.x;
    if (i < n) p[i] = 0.0f;
}

// o[B x 2D] = concat(a[B x D], b[B x D])
__global__ void concat_k(const float* __restrict__ a, const float* __restrict__ b,
                         float* __restrict__ o)
{
    const int i = blockIdx.x * 256 + threadIdx.x;
    if (i >= Bb * 2 * Dd) return;
    const int r = i / (2 * Dd);
    const int c = i % (2 * Dd);
    o[i] = (c < Dd) ? a[r * Dd + c] : b[r * Dd + c - Dd];
}

// in-place softmax over rows of length Mm; grid = B*H rows
__global__ void softmax_k(float* __restrict__ s)
{
    float* row = s + (size_t)blockIdx.x * Mm;
    __shared__ float red[256];
    const int t = threadIdx.x;

    float mx = -1e30f;
    for (int i = t; i < Mm; i += 256) mx = fmaxf(mx, row[i]);
    red[t] = mx;
    __syncthreads();
    for (int o = 128; o; o >>= 1) {
        if (t < o) red[t] = fmaxf(red[t], red[t + o]);
        __syncthreads();
    }
    mx = red[0];
    __syncthreads();

    float sum = 0.0f;
    for (int i = t; i < Mm; i += 256) {
        float e = expf(row[i] - mx);
        row[i] = e;
        sum += e;
    }
    red[t] = sum;
    __syncthreads();
    for (int o = 128; o; o >>= 1) {
        if (t < o) red[t] += red[t + o];
        __syncthreads();
    }
    const float inv = 1.0f / red[0];
    for (int i = t; i < Mm; i += 256) row[i] *= inv;
}

// ---------------- launch ----------------------------------------------------
extern "C" void kernel_launch(void* const* d_in, const int* in_sizes, int n_in,
                              void* d_out, int out_size)
{
    (void)in_sizes; (void)n_in; (void)out_size;
    const float* x    = (const float*)d_in[0];
    const float* mk   = (const float*)d_in[1];
    const float* mv   = (const float*)d_in[2];
    const float* Wq   = (const float*)d_in[3];
    const float* bq   = (const float*)d_in[4];
    const float* Wk   = (const float*)d_in[5];
    const float* bk   = (const float*)d_in[6];
    const float* Wv   = (const float*)d_in[7];
    const float* bv   = (const float*)d_in[8];
    const float* ipw  = (const float*)d_in[9];   // (3D, D)
    const float* ipb  = (const float*)d_in[10];  // (3D,)
    const float* outw = (const float*)d_in[11];
    const float* outb = (const float*)d_in[12];
    const float* gW1  = (const float*)d_in[13];  // (D, 2D)
    const float* gb1  = (const float*)d_in[14];
    const float* gW2  = (const float*)d_in[15];
    const float* gb2  = (const float*)d_in[16];
    const float* iW1  = (const float*)d_in[17];  // (2D, 2D)
    const float* ib1  = (const float*)d_in[18];
    const float* iW2  = (const float*)d_in[19];  // (D, 2D)
    const float* ib2  = (const float*)d_in[20];
    float* out = (float*)d_out;

    const float* Wiq = ipw;
    const float* Wik = ipw + Dd * Dd;
    const float* Wiv = ipw + 2 * Dd * Dd;
    const float* biq = ipb;
    const float* bik = ipb + Dd;
    const float* biv = ipb + 2 * Dd;

    // resolve device-global addresses (host side; not an allocation)
    float *q, *qh, *Wck, *Wcv, *bck, *bcv, *kh, *vh, *scores, *ctx, *ms, *gin, *g1, *gated, *comb, *i1;
    cudaGetSymbolAddress((void**)&q, g_q);
    cudaGetSymbolAddress((void**)&qh, g_qh);
    cudaGetSymbolAddress((void**)&Wck, g_Wck);
    cudaGetSymbolAddress((void**)&Wcv, g_Wcv);
    cudaGetSymbolAddress((void**)&bck, g_bck);
    cudaGetSymbolAddress((void**)&bcv, g_bcv);
    cudaGetSymbolAddress((void**)&kh, g_kh);
    cudaGetSymbolAddress((void**)&vh, g_vh);
    cudaGetSymbolAddress((void**)&scores, g_scores);
    cudaGetSymbolAddress((void**)&ctx, g_ctx);
    cudaGetSymbolAddress((void**)&ms, g_ms);
    cudaGetSymbolAddress((void**)&gin, g_gin);
    cudaGetSymbolAddress((void**)&g1, g_g1);
    cudaGetSymbolAddress((void**)&gated, g_gated);
    cudaGetSymbolAddress((void**)&comb, g_comb);
    cudaGetSymbolAddress((void**)&i1, g_i1);

    const dim3 blk(256);

    // 1) combined biases: bck = bik + Wik@bk ; bcv = biv + Wiv@bv
    bias_combine_k<<<Dd / 8, dim3(32, 8)>>>(Wik, bk, bik, bck);
    bias_combine_k<<<Dd / 8, dim3(32, 8)>>>(Wiv, bv, biv, bcv);

    // 2) combined weights: Wck = Wik @ Wk, Wcv = Wiv @ Wv   (NN, 1024^3)
    gemm_k<128, 128, 8, 8, 8, true, false><<<dim3(8, 8, 1), blk>>>(
        Wik, Wk, Wck, Dd, Dd, Dd, Dd, Dd, Dd, 0, 0, 0, 1, 1.0f, nullptr, 0, nullptr);
    gemm_k<128, 128, 8, 8, 8, true, false><<<dim3(8, 8, 1), blk>>>(
        Wiv, Wv, Wcv, Dd, Dd, Dd, Dd, Dd, Dd, 0, 0, 0, 1, 1.0f, nullptr, 0, nullptr);

    // 3) kh = keys @ Wck^T + bck ; vh = values @ Wcv^T + bcv   (TN, 8192x1024x1024)
    gemm_k<128, 128, 8, 8, 8, false, false><<<dim3(8, 64, 1), blk>>>(
        mk, Wck, kh, Mm, Dd, Dd, Dd, Dd, Dd, 0, 0, 0, 1, 1.0f, bck, 0, nullptr);
    gemm_k<128, 128, 8, 8, 8, false, false><<<dim3(8, 64, 1), blk>>>(
        mv, Wcv, vh, Mm, Dd, Dd, Dd, Dd, Dd, 0, 0, 0, 1, 1.0f, bcv, 0, nullptr);

    // 4) q = x @ Wq^T + bq ; qh = q @ Wiq^T + biq   (TN small)
    gemm_k<64, 64, 16, 4, 4, false, false><<<dim3(16, 1, 1), blk>>>(
        x, Wq, q, Bb, Dd, Dd, Dd, Dd, Dd, 0, 0, 0, 1, 1.0f, bq, 0, nullptr);
    gemm_k<64, 64, 16, 4, 4, false, false><<<dim3(16, 1, 1), blk>>>(
        q, Wiq, qh, Bb, Dd, Dd, Dd, Dd, Dd, 0, 0, 0, 1, 1.0f, biq, 0, nullptr);

    // 5) scores[b,h,m] = 0.125 * sum_d qh[b,h*64+d]*kh[m,h*64+d]   (batched TN per head)
    gemm_k<64, 64, 16, 4, 4, false, false><<<dim3(Mm / 64, 1, Hh), blk>>>(
        qh, kh, scores, Bb, Mm, HDd, Dd, Dd, Hh * Mm, HDd, HDd, Mm,
        1, 0.125f, nullptr, 0, nullptr);

    // 6) softmax over m
    softmax_k<<<Bb * Hh, blk>>>(scores);

    // 7) ctx = attn @ vh   (batched NN per head, split-K=8, atomic accumulate)
    zero_k<<<(Bb * Dd + 255) / 256, blk>>>(ctx, Bb * Dd);
    gemm_k<64, 64, 16, 4, 4, true, true><<<dim3(1, 1, Hh * 8), blk>>>(
        scores, vh, ctx, Bb, HDd, Mm, Hh * Mm, Dd, Dd, Mm, HDd, HDd,
        8, 1.0f, nullptr, 0, nullptr);

    // 8) memory_signal = ctx @ out_w^T + out_b
    gemm_k<64, 64, 16, 4, 4, false, false><<<dim3(16, 1, 1), blk>>>(
        ctx, outw, ms, Bb, Dd, Dd, Dd, Dd, Dd, 0, 0, 0, 1, 1.0f, outb, 0, nullptr);

    // 9) gate path: gin = [x, ms]; g1 = relu(gin@gW1^T+gb1); gated = sigmoid(g1@gW2^T+gb2)*ms
    concat_k<<<(Bb * 2 * Dd + 255) / 256, blk>>>(x, ms, gin);
    gemm_k<64, 64, 16, 4, 4, false, false><<<dim3(16, 1, 1), blk>>>(
        gin, gW1, g1, Bb, Dd, 2 * Dd, 2 * Dd, 2 * Dd, Dd, 0, 0, 0, 1, 1.0f, gb1, 1, nullptr);
    gemm_k<64, 64, 16, 4, 4, false, false><<<dim3(16, 1, 1), blk>>>(
        g1, gW2, gated, Bb, Dd, Dd, Dd, Dd, Dd, 0, 0, 0, 1, 1.0f, gb2, 2, ms);

    // 10) output path: comb = [x, gated]; i1 = relu(comb@iW1^T+ib1); out = i1@iW2^T+ib2
    concat_k<<<(Bb * 2 * Dd + 255) / 256, blk>>>(x, gated, comb);
    gemm_k<64, 64, 16, 4, 4, false, false><<<dim3(32, 1, 1), blk>>>(
        comb, iW1, i1, Bb, 2 * Dd, 2 * Dd, 2 * Dd, 2 * Dd, 2 * Dd, 0, 0, 0, 1, 1.0f, ib1, 1, nullptr);
    gemm_k<64, 64, 16, 4, 4, false, false><<<dim3(16, 1, 1), blk>>>(
        i1, iW2, out, Bb, Dd, 2 * Dd, 2 * Dd, 2 * Dd, Dd, 0, 0, 0, 1, 1.0f, ib2, 0, nullptr);
}

// round 6
// speedup vs baseline: 1.7260x; 1.7245x over previous
#include <cuda_runtime.h>
#include <cuda_bf16.h>
#include <math.h>
#include <stdint.h>

#define Dd 1024
#define Mm 8192
#define Hh 16
#define Bb 64

typedef __nv_bfloat16 bf16;

// ---------------- scratch (device globals) ----------------------------------
#define DA __device__ __align__(16)
DA bf16 s_WkT[Dd * 3 * Dd];
DA bf16 s_WvT[Dd * 3 * Dd];
DA bf16 s_Wik[Dd * 3 * Dd];
DA bf16 s_Wiv[Dd * 3 * Dd];
DA bf16 s_Wck[Dd * 3 * Dd];
DA bf16 s_Wcv[Dd * 3 * Dd];
DA bf16 s_keys[Mm * 3 * Dd];
DA bf16 s_vals[Mm * 3 * Dd];
DA bf16 s_kh[Mm * 3 * Dd];
DA bf16 s_vhT[Dd * 3 * Mm];
DA bf16 s_attn[Bb * Hh * 3 * Mm];
DA bf16 s_x[Bb * 3 * Dd];
DA bf16 s_Wq[Dd * 3 * Dd];
DA bf16 s_q[Bb * 3 * Dd];
DA bf16 s_Wiq[Dd * 3 * Dd];
DA bf16 s_qh[Bb * 3 * Dd];
DA bf16 s_ctx[Bb * 3 * Dd];
DA bf16 s_outw[Dd * 3 * Dd];
DA bf16 s_gin[Bb * 6 * Dd];
DA bf16 s_gW1[Dd * 6 * Dd];
DA bf16 s_g1[Bb * 3 * Dd];
DA bf16 s_gW2[Dd * 3 * Dd];
DA bf16 s_comb[Bb * 6 * Dd];
DA bf16 s_iW1[2 * Dd * 6 * Dd];
DA bf16 s_i1[Bb * 6 * Dd];
DA bf16 s_iW2[Dd * 6 * Dd];

DA float f_Wck[Dd * Dd];
DA float f_Wcv[Dd * Dd];
DA float f_kh[Mm * Dd];
DA float f_vh[Mm * Dd];
DA float f_q[Bb * Dd];
DA float f_qh[Bb * Dd];
DA float f_scores[Bb * Hh * Mm];
DA float f_ctx[Bb * Dd];
DA float f_ms[Bb * Dd];
DA float f_gin[Bb * 2 * Dd];
DA float f_g1[Bb * Dd];
DA float f_gated[Bb * Dd];
DA float f_comb[Bb * 2 * Dd];
DA float f_i1[Bb * 2 * Dd];
DA float f_bck[Dd];
DA float f_bcv[Dd];

// ---------------- helpers ----------------------------------------------------
__device__ __forceinline__ uint32_t sptr(const void* p)
{
    return (uint32_t)__cvta_generic_to_shared(p);
}

__device__ __forceinline__ void cpasync16(const bf16* g, uint32_t s)
{
    asm volatile("cp.async.ca.shared.global [%0], [%1], 16;" :: "r"(s), "l"(g));
}

__device__ __forceinline__ void ldm4(uint32_t s, uint32_t& r0, uint32_t& r1,
                                     uint32_t& r2, uint32_t& r3)
{
    asm volatile("ldmatrix.sync.aligned.m8n8.x4.shared.b16 {%0,%1,%2,%3}, [%4];"
                 : "=r"(r0), "=r"(r1), "=r"(r2), "=r"(r3) : "r"(s));
}

__device__ __forceinline__ void mma16816(float* c, const uint32_t* a, const uint32_t* b)
{
    asm volatile(
        "mma.sync.aligned.m16n8k16.row.col.f32.bf16.bf16.f32 "
        "{%0,%1,%2,%3}, {%4,%5,%6,%7}, {%8,%9}, {%0,%1,%2,%3};"
        : "+f"(c[0]), "+f"(c[1]), "+f"(c[2]), "+f"(c[3])
        : "r"(a[0]), "r"(a[1]), "r"(a[2]), "r"(a[3]), "r"(b[0]), "r"(b[1]));
}

// ---------------- bf16-split tensor GEMM (TN) --------------------------------
// C[m,n] = act(alpha * sum_k A[m,k]*B[n,k] + bias[n]) * mul[m,n]
// A: M x K bf16 row-major (lda), B: N x K bf16 row-major (ldb), C: M x N fp32.
// Batched via blockIdx.z = batch*nsplit + split; split-K accumulates atomically.
template <int BM, int BN, bool ATOMIC>
__global__ void __launch_bounds__(256) mma_gemm(
    const bf16* __restrict__ A, const bf16* __restrict__ B, float* __restrict__ C,
    int K, int lda, int ldb, int ldc,
    long sA, long sB, long sC, int nsplit, float alpha,
    const float* __restrict__ bias, int act, const float* __restrict__ mul)
{
    constexpr int BK = 32, SK = 40;
    constexpr int WARPS_M = BM / 32;
    constexpr int WARPS_N = 8 / WARPS_M;
    constexpr int WN = BN / WARPS_N;
    constexpr int MI = 2, NI = WN / 8;
    constexpr int CA = BM * 4 / 256;
    constexpr int CB = BN * 4 / 256;

    __shared__ bf16 As[2][BM * SK];
    __shared__ bf16 Bs[2][BN * SK];

    const int tid = threadIdx.x;
    const int lane = tid & 31;
    const int warp = tid >> 5;
    const int wm = (warp % WARPS_M) * 32;
    const int wn = (warp / WARPS_M) * WN;

    const long z = blockIdx.z;
    const long batch = z / nsplit;
    const int split = (int)(z % nsplit);
    A += batch * sA;
    B += batch * sB;
    C += batch * sC;

    const int Ks = K / nsplit;
    const int kbase = split * Ks;
    const int NT = Ks / BK;
    const int m0 = blockIdx.y * BM;
    const int n0 = blockIdx.x * BN;

    float acc[MI][NI][4];
#pragma unroll
    for (int i = 0; i < MI; i++)
#pragma unroll
        for (int j = 0; j < NI; j++)
#pragma unroll
            for (int q = 0; q < 4; q++) acc[i][j][q] = 0.0f;

    // ---- tile loaders (cp.async, 16B chunks)
    auto loadT = [&](int buf, int kt) {
        const int k0 = kbase + kt * BK;
#pragma unroll
        for (int i = 0; i < CA; i++) {
            int cid = tid + i * 256;
            int r = cid >> 2, c = (cid & 3) * 8;
            cpasync16(A + (long)(m0 + r) * lda + k0 + c, sptr(&As[buf][r * SK + c]));
        }
#pragma unroll
        for (int i = 0; i < CB; i++) {
            int cid = tid + i * 256;
            int r = cid >> 2, c = (cid & 3) * 8;
            cpasync16(B + (long)(n0 + r) * ldb + k0 + c, sptr(&Bs[buf][r * SK + c]));
        }
        asm volatile("cp.async.commit_group;");
    };

    loadT(0, 0);

    for (int kt = 0; kt < NT; kt++) {
        asm volatile("cp.async.wait_group 0;");
        __syncthreads();
        const int buf = kt & 1;
        if (kt + 1 < NT) loadT(buf ^ 1, kt + 1);

#pragma unroll
        for (int ki = 0; ki < 2; ki++) {
            uint32_t a[MI][4], b[NI][2];
#pragma unroll
            for (int mi = 0; mi < MI; mi++) {
                int row = wm + mi * 16 + (lane & 15);
                int col = ki * 16 + (lane >> 4) * 8;
                ldm4(sptr(&As[buf][row * SK + col]),
                     a[mi][0], a[mi][1], a[mi][2], a[mi][3]);
            }
#pragma unroll
            for (int nj = 0; nj < NI; nj += 2) {
                int row = wn + nj * 8 + (lane & 15);
                int col = ki * 16 + (lane >> 4) * 8;
                uint32_t r0, r1, r2, r3;
                ldm4(sptr(&Bs[buf][row * SK + col]), r0, r1, r2, r3);
                b[nj][0] = r0;     b[nj][1] = r2;
                b[nj + 1][0] = r1; b[nj + 1][1] = r3;
            }
#pragma unroll
            for (int mi = 0; mi < MI; mi++)
#pragma unroll
                for (int nj = 0; nj < NI; nj++)
                    mma16816(acc[mi][nj], a[mi], b[nj]);
        }
        __syncthreads();
    }

    // ---- epilogue
#pragma unroll
    for (int mi = 0; mi < MI; mi++) {
#pragma unroll
        for (int nj = 0; nj < NI; nj++) {
            const int r = m0 + wm + mi * 16 + (lane >> 2);
            const int c = n0 + wn + nj * 8 + (lane & 3) * 2;
#pragma unroll
            for (int q = 0; q < 4; q++) {
                const int rr = r + (q >> 1) * 8;
                const int cc = c + (q & 1);
                float v = acc[mi][nj][q] * alpha;
                if (ATOMIC) {
                    atomicAdd(&C[(long)rr * ldc + cc], v);
                } else {
                    if (bias) v += bias[cc];
                    if (act == 1) v = fmaxf(v, 0.0f);
                    else if (act == 2) v = 1.0f / (1.0f + expf(-v));
                    if (mul) v *= mul[(long)rr * ldc + cc];
                    C[(long)rr * ldc + cc] = v;
                }
            }
        }
    }
}

// ---------------- conversion kernels -----------------------------------------
// split: in R x K fp32 (ldin) -> out R x 3K bf16. mode 0 (A): [h|h|l]; 1 (B): [h|l|h]
__global__ void split_k(const float* __restrict__ in, bf16* __restrict__ out,
                        int R, int K, int ldin, int mode)
{
    long i = (long)blockIdx.x * 256 + threadIdx.x;
    if (i >= (long)R * K) return;
    int r = (int)(i / K), k = (int)(i % K);
    float x = in[(long)r * ldin + k];
    bf16 h = __float2bfloat16(x);
    bf16 l = __float2bfloat16(x - __bfloat162float(h));
    bf16* o = out + (long)r * 3 * K;
    if (mode == 0) { o[k] = h; o[K + k] = h; o[2 * K + k] = l; }
    else           { o[k] = h; o[K + k] = l; o[2 * K + k] = h; }
}

// per-head split: in R x 1024 -> out R x 3072, head-major blocks of 192
__global__ void headsplit_k(const float* __restrict__ in, bf16* __restrict__ out,
                            int R, int mode)
{
    long i = (long)blockIdx.x * 256 + threadIdx.x;
    if (i >= (long)R * Dd) return;
    int r = (int)(i / Dd), c = (int)(i % Dd);
    int h = c >> 6, j = c & 63;
    float x = in[i];
    bf16 hi = __float2bfloat16(x);
    bf16 lo = __float2bfloat16(x - __bfloat162float(hi));
    bf16* o = out + (long)r * 3 * Dd + h * 192 + j;
    if (mode == 0) { o[0] = hi; o[64] = hi; o[128] = lo; }
    else           { o[0] = hi; o[64] = lo; o[128] = hi; }
}

// transpose + B-split: in Kr x Nc fp32 row-major -> out Nc x 3Kr bf16 [h|l|h]
__global__ void tsplit_k(const float* __restrict__ in, bf16* __restrict__ out,
                         int Kr, int Nc)
{
    __shared__ float t[32][33];
    int k0 = blockIdx.x * 32, n0 = blockIdx.y * 32;
    int tx = threadIdx.x, ty = threadIdx.y;
#pragma unroll
    for (int i = 0; i < 32; i += 8)
        t[ty + i][tx] = in[(long)(k0 + ty + i) * Nc + n0 + tx];
    __syncthreads();
#pragma unroll
    for (int i = 0; i < 32; i += 8) {
        int n = n0 + ty + i, k = k0 + tx;
        float x = t[tx][ty + i];
        bf16 h = __float2bfloat16(x);
        bf16 l = __float2bfloat16(x - __bfloat162float(h));
        bf16* o = out + (long)n * 3 * Kr + k;
        o[0] = h; o[Kr] = l; o[2 * Kr] = h;
    }
}

// ---------------- misc kernels (fp32) ----------------------------------------
__global__ void bias_combine_k(const float* __restrict__ W, const float* __restrict__ b1,
                               const float* __restrict__ b2, float* __restrict__ out)
{
    const int row = blockIdx.x * blockDim.y + threadIdx.y;
    const int lane = threadIdx.x;
    float s = 0.0f;
    for (int c = lane; c < Dd; c += 32) s += W[row * Dd + c] * b1[c];
#pragma unroll
    for (int o = 16; o; o >>= 1) s += __shfl_down_sync(0xffffffffu, s, o);
    if (lane == 0) out[row] = s + b2[row];
}

__global__ void zero_k(float* p, int n)
{
    int i = blockIdx.x * 256 + threadIdx.x;
    if (i < n) p[i] = 0.0f;
}

__global__ void concat_k(const float* __restrict__ a, const float* __restrict__ b,
                         float* __restrict__ o)
{
    int i = blockIdx.x * 256 + threadIdx.x;
    if (i >= Bb * 2 * Dd) return;
    int r = i / (2 * Dd), c = i % (2 * Dd);
    o[i] = (c < Dd) ? a[r * Dd + c] : b[r * Dd + c - Dd];
}

__global__ void softmax_k(float* __restrict__ s)
{
    float* row = s + (size_t)blockIdx.x * Mm;
    __shared__ float red[256];
    const int t = threadIdx.x;
    float mx = -1e30f;
    for (int i = t; i < Mm; i += 256) mx = fmaxf(mx, row[i]);
    red[t] = mx;
    __syncthreads();
    for (int o = 128; o; o >>= 1) { if (t < o) red[t] = fmaxf(red[t], red[t + o]); __syncthreads(); }
    mx = red[0];
    __syncthreads();
    float sum = 0.0f;
    for (int i = t; i < Mm; i += 256) { float e = expf(row[i] - mx); row[i] = e; sum += e; }
    red[t] = sum;
    __syncthreads();
    for (int o = 128; o; o >>= 1) { if (t < o) red[t] += red[t + o]; __syncthreads(); }
    const float inv = 1.0f / red[0];
    for (int i = t; i < Mm; i += 256) row[i] *= inv;
}

// ---------------- launch ------------------------------------------------------
#define SYM(v, g) cudaGetSymbolAddress((void**)&v, g)
#define GRD(n) dim3((unsigned)(((long)(n) + 255) / 256))

extern "C" void kernel_launch(void* const* d_in, const int* in_sizes, int n_in,
                              void* d_out, int out_size)
{
    (void)in_sizes; (void)n_in; (void)out_size;
    const float* x    = (const float*)d_in[0];
    const float* mk   = (const float*)d_in[1];
    const float* mv   = (const float*)d_in[2];
    const float* Wq   = (const float*)d_in[3];
    const float* bq   = (const float*)d_in[4];
    const float* Wk   = (const float*)d_in[5];
    const float* bk   = (const float*)d_in[6];
    const float* Wv   = (const float*)d_in[7];
    const float* bv   = (const float*)d_in[8];
    const float* ipw  = (const float*)d_in[9];
    const float* ipb  = (const float*)d_in[10];
    const float* outw = (const float*)d_in[11];
    const float* outb = (const float*)d_in[12];
    const float* gW1  = (const float*)d_in[13];
    const float* gb1  = (const float*)d_in[14];
    const float* gW2  = (const float*)d_in[15];
    const float* gb2  = (const float*)d_in[16];
    const float* iW1  = (const float*)d_in[17];
    const float* ib1  = (const float*)d_in[18];
    const float* iW2  = (const float*)d_in[19];
    const float* ib2  = (const float*)d_in[20];
    float* out = (float*)d_out;

    const float* Wiq = ipw;
    const float* Wik = ipw + Dd * Dd;
    const float* Wiv = ipw + 2 * Dd * Dd;
    const float* biq = ipb;
    const float* bik = ipb + Dd;
    const float* biv = ipb + 2 * Dd;

    bf16 *pWkT, *pWvT, *pWik, *pWiv, *pWck, *pWcv, *pkeys, *pvals, *pkh, *pvhT, *pattn;
    bf16 *px, *pWq, *pq, *pWiq, *pqh, *pctx, *poutw, *pgin, *pgW1, *pg1, *pgW2;
    bf16 *pcomb, *piW1, *pi1, *piW2;
    float *fWck, *fWcv, *fkh, *fvh, *fq, *fqh, *fsc, *fctx, *fms, *fgin, *fg1, *fgated;
    float *fcomb, *fi1, *fbck, *fbcv;

    SYM(pWkT, s_WkT); SYM(pWvT, s_WvT); SYM(pWik, s_Wik); SYM(pWiv, s_Wiv);
    SYM(pWck, s_Wck); SYM(pWcv, s_Wcv); SYM(pkeys, s_keys); SYM(pvals, s_vals);
    SYM(pkh, s_kh); SYM(pvhT, s_vhT); SYM(pattn, s_attn);
    SYM(px, s_x); SYM(pWq, s_Wq); SYM(pq, s_q); SYM(pWiq, s_Wiq); SYM(pqh, s_qh);
    SYM(pctx, s_ctx); SYM(poutw, s_outw); SYM(pgin, s_gin); SYM(pgW1, s_gW1);
    SYM(pg1, s_g1); SYM(pgW2, s_gW2); SYM(pcomb, s_comb); SYM(piW1, s_iW1);
    SYM(pi1, s_i1); SYM(piW2, s_iW2);
    SYM(fWck, f_Wck); SYM(fWcv, f_Wcv); SYM(fkh, f_kh); SYM(fvh, f_vh);
    SYM(fq, f_q); SYM(fqh, f_qh); SYM(fsc, f_scores); SYM(fctx, f_ctx);
    SYM(fms, f_ms); SYM(fgin, f_gin); SYM(fg1, f_g1); SYM(fgated, f_gated);
    SYM(fcomb, f_comb); SYM(fi1, f_i1); SYM(fbck, f_bck); SYM(fbcv, f_bcv);

    const dim3 blk(256);
    const dim3 tb(32, 8);

    // 1) weight transposes / splits + combined biases
    tsplit_k<<<dim3(Dd / 32, Dd / 32), tb>>>(Wk, pWkT, Dd, Dd);
    tsplit_k<<<dim3(Dd / 32, Dd / 32), tb>>>(Wv, pWvT, Dd, Dd);
    split_k<<<GRD(Dd * Dd), blk>>>(Wik, pWik, Dd, Dd, Dd, 0);
    split_k<<<GRD(Dd * Dd), blk>>>(Wiv, pWiv, Dd, Dd, Dd, 0);
    bias_combine_k<<<Dd / 8, tb>>>(Wik, bk, bik, fbck);
    bias_combine_k<<<Dd / 8, tb>>>(Wiv, bv, biv, fbcv);

    // 2) combined weights: Wck = Wik @ Wk, Wcv = Wiv @ Wv
    mma_gemm<128, 128, false><<<dim3(8, 8, 1), blk>>>(
        pWik, pWkT, fWck, 3 * Dd, 3 * Dd, 3 * Dd, Dd, 0, 0, 0, 1, 1.0f, nullptr, 0, nullptr);
    mma_gemm<128, 128, false><<<dim3(8, 8, 1), blk>>>(
        pWiv, pWvT, fWcv, 3 * Dd, 3 * Dd, 3 * Dd, Dd, 0, 0, 0, 1, 1.0f, nullptr, 0, nullptr);
    split_k<<<GRD(Dd * Dd), blk>>>(fWck, pWck, Dd, Dd, Dd, 1);
    split_k<<<GRD(Dd * Dd), blk>>>(fWcv, pWcv, Dd, Dd, Dd, 1);

    // 3) kh = keys @ Wck^T + bck ; vh = values @ Wcv^T + bcv
    split_k<<<GRD((long)Mm * Dd), blk>>>(mk, pkeys, Mm, Dd, Dd, 0);
    split_k<<<GRD((long)Mm * Dd), blk>>>(mv, pvals, Mm, Dd, Dd, 0);
    mma_gemm<128, 128, false><<<dim3(8, 64, 1), blk>>>(
        pkeys, pWck, fkh, 3 * Dd, 3 * Dd, 3 * Dd, Dd, 0, 0, 0, 1, 1.0f, fbck, 0, nullptr);
    mma_gemm<128, 128, false><<<dim3(8, 64, 1), blk>>>(
        pvals, pWcv, fvh, 3 * Dd, 3 * Dd, 3 * Dd, Dd, 0, 0, 0, 1, 1.0f, fbcv, 0, nullptr);
    headsplit_k<<<GRD((long)Mm * Dd), blk>>>(fkh, pkh, Mm, 1);
    tsplit_k<<<dim3(Mm / 32, Dd / 32), tb>>>(fvh, pvhT, Mm, Dd);

    // 4) q = x @ Wq^T + bq ; qh = q @ Wiq^T + biq
    split_k<<<GRD(Bb * Dd), blk>>>(x, px, Bb, Dd, Dd, 0);
    split_k<<<GRD(Dd * Dd), blk>>>(Wq, pWq, Dd, Dd, Dd, 1);
    mma_gemm<64, 128, false><<<dim3(8, 1, 1), blk>>>(
        px, pWq, fq, 3 * Dd, 3 * Dd, 3 * Dd, Dd, 0, 0, 0, 1, 1.0f, bq, 0, nullptr);
    split_k<<<GRD(Bb * Dd), blk>>>(fq, pq, Bb, Dd, Dd, 0);
    split_k<<<GRD(Dd * Dd), blk>>>(Wiq, pWiq, Dd, Dd, Dd, 1);
    mma_gemm<64, 128, false><<<dim3(8, 1, 1), blk>>>(
        pq, pWiq, fqh, 3 * Dd, 3 * Dd, 3 * Dd, Dd, 0, 0, 0, 1, 1.0f, biq, 0, nullptr);
    headsplit_k<<<GRD(Bb * Dd), blk>>>(fqh, pqh, Bb, 0);

    // 5) scores (batched per head): K' = 192, alpha = 1/8
    mma_gemm<64, 128, false><<<dim3(Mm / 128, 1, Hh), blk>>>(
        pqh, pkh, fsc, 192, 3 * Dd, 3 * Dd, Hh * Mm,
        192, 192, Mm, 1, 0.125f, nullptr, 0, nullptr);

    // 6) softmax + split attn
    softmax_k<<<Bb * Hh, blk>>>(fsc);
    split_k<<<GRD((long)Bb * Hh * Mm), blk>>>(fsc, pattn, Bb * Hh, Mm, Mm, 0);

    // 7) ctx = attn @ vh (batched per head, split-K = 8, atomic)
    zero_k<<<GRD(Bb * Dd), blk>>>(fctx, Bb * Dd);
    mma_gemm<64, 64, true><<<dim3(1, 1, Hh * 8), blk>>>(
        pattn, pvhT, fctx, 3 * Mm, Hh * 3 * Mm, 3 * Mm, Dd,
        3 * Mm, (long)64 * 3 * Mm, 64, 8, 1.0f, nullptr, 0, nullptr);

    // 8) ms = ctx @ out_w^T + out_b
    split_k<<<GRD(Bb * Dd), blk>>>(fctx, pctx, Bb, Dd, Dd, 0);
    split_k<<<GRD(Dd * Dd), blk>>>(outw, poutw, Dd, Dd, Dd, 1);
    mma_gemm<64, 128, false><<<dim3(8, 1, 1), blk>>>(
        pctx, poutw, fms, 3 * Dd, 3 * Dd, 3 * Dd, Dd, 0, 0, 0, 1, 1.0f, outb, 0, nullptr);

    // 9) gate: g1 = relu([x|ms]@gW1^T+gb1); gated = sigmoid(g1@gW2^T+gb2)*ms
    concat_k<<<GRD(Bb * 2 * Dd), blk>>>(x, fms, fgin);
    split_k<<<GRD(Bb * 2 * Dd), blk>>>(fgin, pgin, Bb, 2 * Dd, 2 * Dd, 0);
    split_k<<<GRD(Dd * 2 * Dd), blk>>>(gW1, pgW1, Dd, 2 * Dd, 2 * Dd, 1);
    mma_gemm<64, 128, false><<<dim3(8, 1, 1), blk>>>(
        pgin, pgW1, fg1, 6 * Dd, 6 * Dd, 6 * Dd, Dd, 0, 0, 0, 1, 1.0f, gb1, 1, nullptr);
    split_k<<<GRD(Bb * Dd), blk>>>(fg1, pg1, Bb, Dd, Dd, 0);
    split_k<<<GRD(Dd * Dd), blk>>>(gW2, pgW2, Dd, Dd, Dd, 1);
    mma_gemm<64, 128, false><<<dim3(8, 1, 1), blk>>>(
        pg1, pgW2, fgated, 3 * Dd, 3 * Dd, 3 * Dd, Dd, 0, 0, 0, 1, 1.0f, gb2, 2, fms);

    // 10) out: i1 = relu([x|gated]@iW1^T+ib1); out = i1@iW2^T+ib2
    concat_k<<<GRD(Bb * 2 * Dd), blk>>>(x, fgated, fcomb);
    split_k<<<GRD(Bb * 2 * Dd), blk>>>(fcomb, pcomb, Bb, 2 * Dd, 2 * Dd, 0);
    split_k<<<GRD(2 * Dd * 2 * Dd), blk>>>(iW1, piW1, 2 * Dd, 2 * Dd, 2 * Dd, 1);
    mma_gemm<64, 128, false><<<dim3(16, 1, 1), blk>>>(
        pcomb, piW1, fi1, 6 * Dd, 6 * Dd, 6 * Dd, 2 * Dd, 0, 0, 0, 1, 1.0f, ib1, 1, nullptr);
    split_k<<<GRD(Bb * 2 * Dd), blk>>>(fi1, pi1, Bb, 2 * Dd, 2 * Dd, 0);
    split_k<<<GRD(Dd * 2 * Dd), blk>>>(iW2, piW2, Dd, 2 * Dd, 2 * Dd, 1);
    mma_gemm<64, 128, false><<<dim3(8, 1, 1), blk>>>(
        pi1, piW2, out, 6 * Dd, 6 * Dd, 6 * Dd, Dd, 0, 0, 0, 1, 1.0f, ib2, 0, nullptr);
}